// round 12
// baseline (speedup 1.0000x reference)
#include <cuda_runtime.h>
#include <cuda_bf16.h>
#include <cstdint>
#include <cstddef>

// ---------------- arch gate ----------------
// tcgen05 is only emittable when nvcc compiles an arch-specific (sm_103a) or
// family-specific pass. Proven live in R8 (fallback kernel compiled empty).
#if defined(__CUDA_ARCH__) && (defined(__CUDA_ARCH_FEAT_SM103_ALL) || defined(__CUDA_ARCH_SPECIFIC__) || defined(__CUDA_ARCH_FAMILY_SPECIFIC__))
#define TCOK 1
#else
#define TCOK 0
#endif

// ---------------- Problem constants ----------------
#define N_BATCH 32768
#define N_EMBED 1024
#define N_HEADS 8
#define HD 128
#define N_CODES 1024
#define ZQ_ELEMS ((size_t)N_BATCH*N_EMBED)
#define IDX_ELEMS ((size_t)N_BATCH*N_HEADS)

#define TILE_B 128
#define CHUNK 128
#define NCHUNKS 8
#define NTHREADS 256
#define REFINE_GAP 2.0e-4f

#define TILE_BYTES 32768   // one 128x128 bf16 tile image

// idesc: F32 accum, BF16 a/b, M=128, N=128
#define IDESC 0x08200490u

// ---------------- smem offsets (bytes), tcgen05 kernel ----------------
#define SO_AHI    0
#define SO_ALO    32768
#define SO_B0     65536      // [hi 32768 | lo 32768]
#define SO_B1     131072
#define SO_T      196608     // 32*129*4 = 16512 transpose buf (overlaid later)
#define SO_CSQ    213120     // 1024 floats
#define SO_ZSQ    217216     // 128 floats
#define SO_IDX    218752     // 128 ints
#define SO_FLAG   219264     // 128 ints
#define SO_MBAR   219776     // 2 x 8B
#define SO_TMEMPTR 219792
#define SO_NFLAG  219796
#define SMEM_BYTES 219808

// ---------------- scratch (device globals) ----------------
__device__ __align__(16) unsigned char g_cb_tiles[N_HEADS * NCHUNKS * 2 * TILE_BYTES];
__device__ float g_csq[N_HEADS * N_CODES];

// ---------------- helpers ----------------
__device__ __forceinline__ uint32_t smem_u32(const void* p) {
    uint32_t a;
    asm("{ .reg .u64 t; cvta.to.shared.u64 t, %1; cvt.u32.u64 %0, t; }" : "=r"(a) : "l"(p));
    return a;
}

// blocked SW128 layout for a 128x128 bf16 K-major tile (atoms 8 rows x 64 bf16,
// 16 atom-rows, 2 atom-cols, atom_off = atom_row + atom_col*16) + swizzle.
__device__ __forceinline__ int tile_off128(int row, int d) {
    int off = (((row >> 3) + ((d >> 6) << 4)) << 10) + ((row & 7) << 7) + ((d & 63) << 1);
    return off ^ ((off >> 3) & 0x70);
}

#if TCOK
__device__ __forceinline__ uint32_t elect_one() {
    uint32_t pred;
    asm volatile("{\n\t.reg .pred p;\n\telect.sync _|p, 0xFFFFFFFF;\n\tselp.b32 %0, 1, 0, p;\n\t}" : "=r"(pred));
    return pred;
}

// smem descriptor: SW128, version=1, SBO=64, LBO=1
__device__ __forceinline__ uint64_t make_desc(uint32_t smem_addr) {
    return ((uint64_t)2 << 61) | ((uint64_t)1 << 46) | ((uint64_t)64 << 32) | ((uint64_t)1 << 16)
         | ((uint64_t)(smem_addr >> 4) & 0x3FFF);
}

__device__ __forceinline__ void mma_f16_ss(uint32_t d_tmem, uint64_t a_desc, uint64_t b_desc,
                                           uint32_t idesc, uint32_t accum) {
    asm volatile(
        "{\n\t.reg .pred p;\n\tsetp.ne.u32 p, %4, 0;\n\t"
        "tcgen05.mma.cta_group::1.kind::f16 [%0], %1, %2, %3, {%5,%5,%5,%5}, p;\n\t}"
        :: "r"(d_tmem), "l"(a_desc), "l"(b_desc), "r"(idesc), "r"(accum), "r"(0u) : "memory");
}

__device__ __forceinline__ void mbar_init(uint32_t a, uint32_t cnt) {
    asm volatile("mbarrier.init.shared.b64 [%0], %1;" :: "r"(a), "r"(cnt) : "memory");
}
__device__ __forceinline__ void mbar_wait(uint32_t a, uint32_t parity) {
    asm volatile(
        "{\n\t.reg .pred P1;\n\t"
        "WAIT_LOOP_%=:\n\t"
        "mbarrier.try_wait.parity.acquire.cta.shared::cta.b64 P1, [%0], %1, 0x989680;\n\t"
        "@P1 bra.uni WAIT_DONE_%=;\n\t"
        "bra.uni WAIT_LOOP_%=;\n\t"
        "WAIT_DONE_%=:\n\t}"
        :: "r"(a), "r"(parity) : "memory");
}
__device__ __forceinline__ void cp_async16(uint32_t dst, const void* src) {
    asm volatile("cp.async.cg.shared.global [%0], [%1], 16;" :: "r"(dst), "l"(src) : "memory");
}
__device__ __forceinline__ void cp_commit() { asm volatile("cp.async.commit_group;" ::: "memory"); }
__device__ __forceinline__ void cp_wait1()  { asm volatile("cp.async.wait_group 1;" ::: "memory"); }
__device__ __forceinline__ void cp_wait0()  { asm volatile("cp.async.wait_group 0;" ::: "memory"); }

#define T05_FENCE_AFTER()  asm volatile("tcgen05.fence::after_thread_sync;" ::: "memory")
#define T05_FENCE_BEFORE() asm volatile("tcgen05.fence::before_thread_sync;" ::: "memory")
#define T05_WAIT_LD()      asm volatile("tcgen05.wait::ld.sync.aligned;" ::: "memory")
#define FENCE_PROXY()      asm volatile("fence.proxy.async.shared::cta;" ::: "memory")

#define LDTM_X32(r, addr) \
    asm volatile( \
        "tcgen05.ld.sync.aligned.32x32b.x32.b32 " \
        "{%0, %1, %2, %3, %4, %5, %6, %7, %8, %9, %10, %11, %12, %13, %14, %15, " \
        " %16, %17, %18, %19, %20, %21, %22, %23, %24, %25, %26, %27, %28, %29, %30, %31}, [%32];" \
        : "=r"((r)[0]),  "=r"((r)[1]),  "=r"((r)[2]),  "=r"((r)[3]), \
          "=r"((r)[4]),  "=r"((r)[5]),  "=r"((r)[6]),  "=r"((r)[7]), \
          "=r"((r)[8]),  "=r"((r)[9]),  "=r"((r)[10]), "=r"((r)[11]), \
          "=r"((r)[12]), "=r"((r)[13]), "=r"((r)[14]), "=r"((r)[15]), \
          "=r"((r)[16]), "=r"((r)[17]), "=r"((r)[18]), "=r"((r)[19]), \
          "=r"((r)[20]), "=r"((r)[21]), "=r"((r)[22]), "=r"((r)[23]), \
          "=r"((r)[24]), "=r"((r)[25]), "=r"((r)[26]), "=r"((r)[27]), \
          "=r"((r)[28]), "=r"((r)[29]), "=r"((r)[30]), "=r"((r)[31]) \
        : "r"(addr))
#endif // TCOK

// ---------------- prep kernels ----------------
__global__ void prep_cb_kernel(const float* __restrict__ cb) {
#if TCOK
    const int h = blockIdx.x >> 3;
    const int chunk = blockIdx.x & 7;
    unsigned char* base = g_cb_tiles + ((size_t)(h * NCHUNKS + chunk) * 2) * TILE_BYTES;
    for (int e = threadIdx.x; e < CHUNK * HD; e += blockDim.x) {
        int row = e >> 7;
        int d   = e & 127;
        float f = cb[((size_t)h * N_CODES + chunk * CHUNK + row) * HD + d];
        __nv_bfloat16 hi = __float2bfloat16(f);
        __nv_bfloat16 lo = __float2bfloat16(f - __bfloat162float(hi));
        int off = tile_off128(row, d);
        *(__nv_bfloat16*)(base + off) = hi;
        *(__nv_bfloat16*)(base + TILE_BYTES + off) = lo;
    }
#endif
}

__global__ void prep_csq_kernel(const float* __restrict__ cb) {
#if TCOK
    int g = blockIdx.x * blockDim.x + threadIdx.x;
    if (g >= N_HEADS * N_CODES) return;
    const float4* row = (const float4*)(cb + (size_t)g * HD);
    double s = 0.0;
    #pragma unroll 8
    for (int q = 0; q < HD / 4; q++) {
        float4 v = row[q];
        s += (double)v.x * v.x + (double)v.y * v.y + (double)v.z * v.z + (double)v.w * v.w;
    }
    g_csq[g] = (float)s;
#endif
}

// ---------------- tcgen05 main kernel ----------------
__global__ __launch_bounds__(NTHREADS, 1)
void vq_main_kernel(const float* __restrict__ z, const float* __restrict__ cb,
                    float* __restrict__ out)
{
#if TCOK
    float* zq_out   = out;
    float* idx_out  = out + ZQ_ELEMS;
    float* dist_out = out + ZQ_ELEMS + IDX_ELEMS;

    const int h  = blockIdx.y;
    const int b0 = blockIdx.x * TILE_B;
    const int tid  = threadIdx.x;
    const int wid  = tid >> 5;
    const int lane = tid & 31;
    const int wgid = wid >> 2;          // which 64-col half
    const int subp = wid & 3;           // TMEM subpartition
    const int myrow = subp * 32 + lane; // z row within tile

    extern __shared__ char sm[];
    const uint32_t smb = smem_u32(sm);
    float* csq_s = (float*)(sm + SO_CSQ);
    float* zsq_s = (float*)(sm + SO_ZSQ);
    int*   idxs  = (int*)(sm + SO_IDX);
    int*   flagl = (int*)(sm + SO_FLAG);
    int*   nflag = (int*)(sm + SO_NFLAG);
    float* Tb    = (float*)(sm + SO_T);
    const uint32_t mbar0 = smb + SO_MBAR;
    const uint32_t mbar1 = smb + SO_MBAR + 8;

    if (tid == 0) { mbar_init(mbar0, 1); mbar_init(mbar1, 1); *nflag = 0; }
    if (wid == 0) {
        asm volatile("tcgen05.alloc.cta_group::1.sync.aligned.shared::cta.b32 [%0], %1;"
                     :: "r"(smb + SO_TMEMPTR), "r"(256u) : "memory");
        asm volatile("tcgen05.relinquish_alloc_permit.cta_group::1.sync.aligned;");
    }

    // ---- B chunk 0 and 1 via cp.async FIRST (start the tensor path early) ----
    {
        const unsigned char* src0 = g_cb_tiles + (size_t)(h * NCHUNKS + 0) * 2 * TILE_BYTES;
        #pragma unroll
        for (int i = 0; i < 16; i++)
            cp_async16(smb + SO_B0 + (tid + i * NTHREADS) * 16, src0 + (tid + i * NTHREADS) * 16);
        cp_commit();
        const unsigned char* src1 = g_cb_tiles + (size_t)(h * NCHUNKS + 1) * 2 * TILE_BYTES;
        #pragma unroll
        for (int i = 0; i < 16; i++)
            cp_async16(smb + SO_B1 + (tid + i * NTHREADS) * 16, src1 + (tid + i * NTHREADS) * 16);
        cp_commit();
    }

    // ---- A convert: z rows -> split bf16, swizzled tiles ----
    {
        const int r = tid >> 1;
        const int half = tid & 1;
        const float2* zr = (const float2*)(z + (size_t)(b0 + r) * N_EMBED + h * HD + half * 64);
        #pragma unroll 8
        for (int t = 0; t < 32; t++) {
            float2 v = zr[t];
            int d = half * 64 + t * 2;
            __nv_bfloat16 hx = __float2bfloat16(v.x);
            __nv_bfloat16 hy = __float2bfloat16(v.y);
            __nv_bfloat162 hi2; hi2.x = hx; hi2.y = hy;
            __nv_bfloat162 lo2;
            lo2.x = __float2bfloat16(v.x - __bfloat162float(hx));
            lo2.y = __float2bfloat16(v.y - __bfloat162float(hy));
            int off = tile_off128(r, d);
            *(__nv_bfloat162*)(sm + SO_AHI + off) = hi2;
            *(__nv_bfloat162*)(sm + SO_ALO + off) = lo2;
        }
    }
    #pragma unroll
    for (int i = tid; i < N_CODES; i += NTHREADS) csq_s[i] = g_csq[h * N_CODES + i];

    // ---- zsq: EXACT R3/R8 arithmetic (sequential ascending-k fp32 FMA chain),
    // but with the 32 row loads front-batched into registers (MLP=8 batches)
    // so the chain doesn't serialize 32 L2 round-trips.
    if (tid < TILE_B) {
        const float4* zr = (const float4*)(z + (size_t)(b0 + tid) * N_EMBED + h * HD);
        float4 vbuf[8];
        float s = 0.f;
        #pragma unroll
        for (int blk = 0; blk < 4; blk++) {
            #pragma unroll
            for (int q = 0; q < 8; q++) vbuf[q] = zr[blk * 8 + q];   // batched loads
            #pragma unroll
            for (int q = 0; q < 8; q++) {                            // exact chain order
                float4 v = vbuf[q];
                s = fmaf(v.x, v.x, s);
                s = fmaf(v.y, v.y, s);
                s = fmaf(v.z, v.z, s);
                s = fmaf(v.w, v.w, s);
            }
        }
        zsq_s[tid] = s;
    }
    __syncthreads();

    uint32_t tmem_base;
    asm volatile("ld.shared.b32 %0, [%1];" : "=r"(tmem_base) : "r"(smb + SO_TMEMPTR));

    const uint64_t a_hi = make_desc(smb + SO_AHI);
    const uint64_t a_lo = make_desc(smb + SO_ALO);

    // ---- issue MMA chunk 0 ----
    cp_wait1();
    __syncthreads();
    FENCE_PROXY();
    if (wid == 0 && elect_one()) {
        uint64_t b_hi = make_desc(smb + SO_B0);
        uint64_t b_lo = make_desc(smb + SO_B0 + TILE_BYTES);
        uint32_t first = 0;
        #pragma unroll
        for (int pass = 0; pass < 3; pass++) {
            uint64_t ad = (pass == 2) ? a_lo : a_hi;
            uint64_t bd = (pass == 1) ? b_lo : b_hi;
            #pragma unroll
            for (int k = 0; k < 8; k++) {
                uint64_t off = (k < 4) ? (uint64_t)(k * 2) : (uint64_t)(1024 + (k - 4) * 2);
                mma_f16_ss(tmem_base, ad + off, bd + off, IDESC, first);
                first = 1;
            }
        }
        asm volatile("tcgen05.commit.cta_group::1.mbarrier::arrive::one.shared::cluster.b64 [%0];"
                     :: "r"(mbar0) : "memory");
    }

    float m1 = 3.4e38f, m2 = 3.4e38f;
    int   i1 = 0;
    const float zq2 = zsq_s[myrow];

    for (int kchunk = 0; kchunk < NCHUNKS; kchunk++) {
        const int buf = kchunk & 1;
        const uint32_t mb  = buf ? mbar1 : mbar0;
        const uint32_t mbn = buf ? mbar0 : mbar1;

        mbar_wait(mb, (kchunk >> 1) & 1);
        T05_FENCE_AFTER();

        if (kchunk + 2 < NCHUNKS) {
            const uint32_t dst = smb + (buf ? SO_B1 : SO_B0);
            const unsigned char* src = g_cb_tiles + (size_t)(h * NCHUNKS + kchunk + 2) * 2 * TILE_BYTES;
            #pragma unroll
            for (int i = 0; i < 16; i++)
                cp_async16(dst + (tid + i * NTHREADS) * 16, src + (tid + i * NTHREADS) * 16);
            cp_commit();
        }

        if (kchunk + 1 < NCHUNKS) {
            if (kchunk + 2 < NCHUNKS) cp_wait1(); else cp_wait0();
            __syncthreads();
            FENCE_PROXY();
            if (wid == 0 && elect_one()) {
                const uint32_t bbase = smb + (buf ? SO_B0 : SO_B1);
                uint64_t b_hi = make_desc(bbase);
                uint64_t b_lo = make_desc(bbase + TILE_BYTES);
                const uint32_t dtm = tmem_base + (1 - buf) * CHUNK;
                uint32_t first = 0;
                #pragma unroll
                for (int pass = 0; pass < 3; pass++) {
                    uint64_t ad = (pass == 2) ? a_lo : a_hi;
                    uint64_t bd = (pass == 1) ? b_lo : b_hi;
                    #pragma unroll
                    for (int k = 0; k < 8; k++) {
                        uint64_t off = (k < 4) ? (uint64_t)(k * 2) : (uint64_t)(1024 + (k - 4) * 2);
                        mma_f16_ss(dtm, ad + off, bd + off, IDESC, first);
                        first = 1;
                    }
                }
                asm volatile("tcgen05.commit.cta_group::1.mbarrier::arrive::one.shared::cluster.b64 [%0];"
                             :: "r"(mbn) : "memory");
            }
        }

        // ---- epilogue for chunk kchunk from D[buf] ----
        uint32_t dr[64];
        LDTM_X32(dr,      tmem_base + buf * CHUNK + wgid * 64);
        LDTM_X32(dr + 32, tmem_base + buf * CHUNK + wgid * 64 + 32);
        T05_WAIT_LD();
        T05_FENCE_BEFORE();

        float dv[64];
        const int cb0 = kchunk * CHUNK + wgid * 64;
        #pragma unroll
        for (int j = 0; j < 64; j++) {
            float t = zq2 + csq_s[cb0 + j];
            dv[j] = fmaf(-2.0f, __uint_as_float(dr[j]), t);
        }
        #pragma unroll
        for (int j = 0; j < 64; j++) {
            float v = dv[j];
            if (v < m1) { m2 = m1; m1 = v; i1 = cb0 + j; }
            else if (v < m2) { m2 = v; }
        }

        // ---- transpose passes: 4 x 32 cols through Tb[32][129] ----
        #pragma unroll
        for (int p = 0; p < 4; p++) {
            __syncthreads();
            if (wgid == (p >> 1)) {
                #pragma unroll
                for (int j2 = 0; j2 < 32; j2++) {
                    Tb[j2 * 129 + myrow] = dv[(p & 1) * 32 + j2];
                }
            }
            __syncthreads();
            const int pc = kchunk * CHUNK + p * 32;
            #pragma unroll
            for (int i = 0; i < 16; i++) {
                int r = wid + i * 8;
                float v = Tb[lane * 129 + r];
                dist_out[((size_t)(b0 + r) * N_HEADS + h) * N_CODES + pc + lane] = v;
            }
        }
        __syncthreads();
    }

    // ---- merge the two warpgroup halves per row ----
    float* mv  = Tb;
    int*   mi  = (int*)(Tb + 256);
    float* m2v = Tb + 512;
    mv [wgid * 128 + myrow] = m1;
    mi [wgid * 128 + myrow] = i1;
    m2v[wgid * 128 + myrow] = m2;
    __syncthreads();
    if (tid < TILE_B) {
        float a1 = mv[tid], b1 = mv[128 + tid];
        int   ai = mi[tid], bi = mi[128 + tid];
        float a2 = m2v[tid], b2 = m2v[128 + tid];
        float bv; int bidx; float g2;
        if (b1 < a1 || (b1 == a1 && bi < ai)) { bv = b1; bidx = bi; g2 = fminf(b2, a1); }
        else                                  { bv = a1; bidx = ai; g2 = fminf(a2, b1); }
        idxs[tid] = bidx;
        if (g2 - bv < REFINE_GAP) {
            int slot = atomicAdd(nflag, 1);
            flagl[slot] = tid;
        }
    }
    __syncthreads();

    // ---- fp64 refinement for near-tie rows ----
    const int nf = *nflag;
    float* redv = Tb + 1024;
    int*   redi = (int*)(Tb + 1280);
    for (int f = 0; f < nf; f++) {
        const int r = flagl[f];
        const float zr2 = zsq_s[r];
        const float4* zrow = (const float4*)(z + (size_t)(b0 + r) * N_EMBED + h * HD);
        float bestv = 3.4e38f;
        int   bestk = 0x7fffffff;
        #pragma unroll
        for (int kk = 0; kk < 4; kk++) {
            const int k = tid + kk * NTHREADS;
            const float4* c4 = (const float4*)(cb + ((size_t)h * N_CODES + k) * HD);
            double dot = 0.0, cs2 = 0.0;
            #pragma unroll 8
            for (int q = 0; q < HD / 4; q++) {
                float4 cv = c4[q];
                float4 zv = zrow[q];
                dot += (double)zv.x * cv.x + (double)zv.y * cv.y + (double)zv.z * cv.z + (double)zv.w * cv.w;
                cs2 += (double)cv.x * cv.x + (double)cv.y * cv.y + (double)cv.z * cv.z + (double)cv.w * cv.w;
            }
            float dotf = (float)dot;
            float csqf = (float)cs2;
            float t = zr2 + csqf;
            float d = fmaf(-2.0f, dotf, t);
            if (d < bestv || (d == bestv && k < bestk)) { bestv = d; bestk = k; }
        }
        redv[tid] = bestv;
        redi[tid] = bestk;
        __syncthreads();
        for (int s = NTHREADS / 2; s > 0; s >>= 1) {
            if (tid < s) {
                float v2 = redv[tid + s]; int k2 = redi[tid + s];
                float v1 = redv[tid];     int k1 = redi[tid];
                if (v2 < v1 || (v2 == v1 && k2 < k1)) { redv[tid] = v2; redi[tid] = k2; }
            }
            __syncthreads();
        }
        if (tid == 0) idxs[r] = redi[0];
        __syncthreads();
    }

    if (tid < TILE_B) idx_out[(size_t)(b0 + tid) * N_HEADS + h] = (float)idxs[tid];
    __syncthreads();

    const float4* cb4 = (const float4*)cb;
    float4* zq4 = (float4*)zq_out;
    #pragma unroll
    for (int s = 0; s < TILE_B * (HD / 4) / NTHREADS; s++) {
        int e = tid + s * NTHREADS;
        int r = e >> 5;
        int q = e & 31;
        int c = idxs[r];
        zq4[(size_t)(b0 + r) * (N_EMBED / 4) + h * (HD / 4) + q] =
            cb4[((size_t)h * N_CODES + c) * (HD / 4) + q];
    }

    __syncthreads();
    if (wid == 0) {
        asm volatile("tcgen05.dealloc.cta_group::1.sync.aligned.b32 %0, %1;"
                     :: "r"(tmem_base), "r"(256u));
    }
#endif // TCOK
}

// ---------------- launcher ----------------
extern "C" void kernel_launch(void* const* d_in, const int* in_sizes, int n_in,
                              void* d_out, int out_size)
{
    const float* z  = (const float*)d_in[0];   // [32768, 1024]
    const float* cb = (const float*)d_in[1];   // [8, 1024, 128]
    float* out = (float*)d_out;

    cudaFuncSetAttribute(vq_main_kernel, cudaFuncAttributeMaxDynamicSharedMemorySize, SMEM_BYTES);

    // 3 launches per call -> ncu -s 5 -c 1 profiles launch #6 == vq_main_kernel
    prep_cb_kernel<<<N_HEADS * NCHUNKS, 256>>>(cb);
    prep_csq_kernel<<<(N_HEADS * N_CODES + 255) / 256, 256>>>(cb);

    dim3 grid(N_BATCH / TILE_B, N_HEADS);
    vq_main_kernel<<<grid, NTHREADS, SMEM_BYTES>>>(z, cb, out);
}